// round 14
// baseline (speedup 1.0000x reference)
#include <cuda_runtime.h>
#include <math.h>

#define BB   128            // batch
#define TT   512            // time steps
#define HH   256            // hidden
#define XX   64             // feature / output
#define G3   768            // 3*H
#define HB   (HH * BB)      // 32768 cells per map

// ---------------- device scratch (static: no runtime allocation) ----------------
__device__ float2 g_pair[(size_t)(TT + 1) * HB]; // slot i: {hidden_i, hb_{i-1}} [t][h][b]
__device__ float g_Wc [G3 * HH];                // W_ih @ W_out   [768][256]
__device__ float g_WoT[HH * XX];                // W_out transposed [h][x]
__device__ float g_bc [G3];                     // b_ih + W_ih @ b_out
__device__ float g_m0f[TT], g_m1f[TT];
__device__ int   g_gidx[TT], g_pidx[TT];        // -1 => zero placeholder
__device__ unsigned g_ctr[8 * 64];              // per-group split counters: [bg*64]=low, [bg*64+16]=high

typedef unsigned long long ull;

// ---------------- packed f32x2 ops (Blackwell) ----------------
#define FMA2(d, a, b) asm("fma.rn.f32x2 %0, %1, %2, %3;" \
                          : "=l"(d) : "l"(a), "l"(b), "l"(d))
#define ADD2(d, a, b) asm("add.rn.f32x2 %0, %1, %2;" \
                          : "=l"(d) : "l"(a), "l"(b))
__device__ __forceinline__ float lo32(ull v) {
    return __uint_as_float((unsigned)(v & 0xffffffffull));
}
__device__ __forceinline__ float hi32(ull v) {
    return __uint_as_float((unsigned)(v >> 32));
}

#define CP_ASYNC16(smem_u32, gptr) \
    asm volatile("cp.async.cg.shared.global [%0], [%1], 16;" \
                 :: "r"(smem_u32), "l"(gptr) : "memory")
#define CP_COMMIT()   asm volatile("cp.async.commit_group;" ::: "memory")
#define CP_WAIT(n)    asm volatile("cp.async.wait_group %0;" :: "n"(n) : "memory")

// ---------------- K_wc: Wc = W_ih @ W_out  + W_out transpose ----------------
__global__ void k_wc(const float* __restrict__ W_ih, const float* __restrict__ W_out)
{
    int j = blockIdx.x;
    int k = threadIdx.x;
    if (j < G3) {
        float acc = 0.f;
        #pragma unroll
        for (int x = 0; x < XX; x++)
            acc += W_ih[j * XX + x] * W_out[x * HH + k];
        g_Wc[j * HH + k] = acc;
    } else {
        int idx = (j - G3) * 256 + k;
        int h = idx >> 6, x = idx & 63;
        g_WoT[h * XX + x] = W_out[x * HH + h];
    }
}

// ---------------- K_tab: tables + composed bias ----------------
__global__ void k_init_tables(const int* __restrict__ mask0, const int* __restrict__ mask1,
                              const int* skipp,
                              const float* __restrict__ W_ih, const float* __restrict__ b_ih,
                              const float* __restrict__ b_out)
{
    int tid = threadIdx.x;
    int skip = skipp ? skipp[0] : 4;
    for (int i = tid; i < TT; i += 256) {
        g_m0f[i] = (float)mask0[i];
        g_m1f[i] = (float)mask1[i];
        int pg = (i < skip) ? 2 * i : i - skip;
        g_gidx[i] = (pg < skip) ? -1 : (pg - skip);
        int pp = (i < skip) ? 2 * i + 1 : i - skip;
        g_pidx[i] = (pp < skip) ? -1 : (pp - skip);
    }
    for (int j = tid; j < G3; j += 256) {
        float acc = b_ih[j];
        for (int x = 0; x < XX; x++) acc += W_ih[j * XX + x] * b_out[x];
        g_bc[j] = acc;
    }
}

// ---------------- K_state: init pair slot 0 + counters ----------------
__global__ void k_init_state(const float* __restrict__ h_enc, const int* __restrict__ mask0)
{
    int idx = blockIdx.x * 256 + threadIdx.x;   // 0..32767
    int h = idx >> 7, b = idx & 127;
    float m0 = (float)mask0[0];
    g_pair[idx] = make_float2(m0 * h_enc[b * HH + h], 0.f); // {hidden_0, hb_{-1}=0}
    if (idx < 8 * 64) g_ctr[idx] = 0u;
}

// ---------------- K_main: persistent recurrence + fused output projection --------
// thread: tid = hg*32 + kq*4 + bq  (hg 0..7 warp, kq 0..7, bq 0..3)
// cells: h = h0 + hg*2 + {0,1}, b = b0 + bq*4 + {0..3}; thread's k = {kq + 8j, j=0..31}
// chunk0 = k<128 (producers hgrp 0..7), chunk1 = k>=128 (producers hgrp 8..15)
// sW  [256k][128]: slot (k,hl) at k*128 + ((hl*8) ^ ((k&7)*8)), 6 used floats
// sAct[256k][36] : 16 b-pairs (hid,hb) per row, 4-word row skew from pad 36
// sHist[16][256] : per-thread skip ring
// Projection: at step i>0, sAct's hb lanes = hb_{i-1} => out[t=i-1] for this
// CTA's 16 b and x in [hgrp*4, hgrp*4+4). Runs after arrive, inside poll window.
#define SW_F    (256 * 128)
#define SACT_F  (256 * 36)
#define SHIST_F (16 * 256)
#define SWOT_F  (4 * 256)
#define SRED_F  256
#define SMEM_MAIN ((SW_F + SACT_F + SHIST_F + SWOT_F + SRED_F + 8 + 4 * TT) * 4)

__global__ void __launch_bounds__(256, 1)
k_main(const float* __restrict__ W_hh, const float* __restrict__ b_ih,
       const float* __restrict__ b_hh, const float* __restrict__ h_enc,
       float* __restrict__ out, const float* __restrict__ b_out)
{
    extern __shared__ float sm[];
    float* sW    = sm;
    float* sAct  = sW + SW_F;
    float* sHist = sAct + SACT_F;
    float* sWoT  = sHist + SHIST_F;          // [4x][256k]
    float* sRed  = sWoT + SWOT_F;            // [64 cells][4 partials]
    float* sBo   = sRed + SRED_F;            // 4 b_out values (+pad 8)
    float* sM0   = sBo + 8;
    float* sM1   = sM0 + TT;
    int*   sGI   = (int*)(sM1 + TT);
    int*   sPI   = sGI + TT;

    const int tid = threadIdx.x;
    const int bq  = tid & 3;
    const int kq  = (tid >> 2) & 7;
    const int hg  = tid >> 5;                   // warp id
    const int bg  = blockIdx.x >> 4;            // batch group
    const int hgrp= blockIdx.x & 15;
    const int b0  = bg * 16;
    const int h0  = hgrp * 16;
    const int kb0 = kq & 1, kb1 = (kq >> 1) & 1, kb2 = kq >> 2;

    // owned cell for epilogue
    const int h_m = h0 + hg * 2 + kb2;
    const int b_l = bq * 4 + (kq & 3);
    const int b_m = b0 + b_l;
    const int off = h_m * BB + b_m;             // [h][b] within a pair slot

    // ---- stage weight slice once ----
    for (int idx = tid; idx < 256 * 16; idx += 256) {
        int k = idx >> 4, hl = idx & 15;
        float* d = sW + (size_t)k * 128 + ((hl * 8) ^ ((k & 7) * 8));
        #pragma unroll
        for (int g = 0; g < 3; g++) {
            int row = g * HH + h0 + hl;
            d[2 * g]     = W_hh[row * HH + k];
            d[2 * g + 1] = g_Wc[row * HH + k];
        }
    }
    for (int idx = tid; idx < TT; idx += 256) {
        sM0[idx] = g_m0f[idx]; sM1[idx] = g_m1f[idx];
        sGI[idx] = g_gidx[idx]; sPI[idx] = g_pidx[idx];
    }
    // projection weight slice: x-columns [hgrp*4, +4)
    for (int idx = tid; idx < SWOT_F; idx += 256) {
        int px = idx >> 8, k = idx & 255;
        sWoT[idx] = g_WoT[k * XX + hgrp * 4 + px];
    }
    if (tid < 4) sBo[tid] = b_out[hgrp * 4 + tid];

    // per-owned-cell bias constants
    const float bhh_n = b_hh[2 * HH + h_m];
    const float cr0 = b_hh[h_m]      + b_ih[h_m];
    const float cz0 = b_hh[HH + h_m] + b_ih[HH + h_m];
    const float cn0 = b_ih[2 * HH + h_m];
    const float crN = b_hh[h_m]      + g_bc[h_m];
    const float czN = b_hh[HH + h_m] + g_bc[HH + h_m];
    const float cnN = g_bc[2 * HH + h_m];

    float h_prev  = h_enc[b_m * HH + h_m];
    float hid_own = g_m0f[0] * h_prev;
    __syncthreads();

    unsigned* ctrL = &g_ctr[bg * 64];           // low-h producers (hgrp 0..7)
    unsigned* ctrH = &g_ctr[bg * 64 + 16];      // high-h producers (hgrp 8..15)
    unsigned* myCtr = (hgrp < 8) ? ctrL : ctrH;

    const float* ap0 = sAct + bq * 8;                    // + (kq+8j)*36 per j
    const float* wA  = sW + ((hg * 16) ^ (kq * 8));      // + (kq+8j)*128 per j
    const float* wB  = sW + (((hg * 16) ^ (kq * 8)) ^ 8);
    const int q_me   = tid & 7;                          // staging lane mapping
    const int k_me   = tid >> 3;                         // 0..31 within a 256-thread pass

    // projection mapping (cell c = pb*4 + px)
    const int pb = tid & 15, px = (tid >> 4) & 3, pk = tid >> 6;
    const float* pA = sAct + (size_t)(pk * 64) * 36 + pb * 2 + 1;
    const float* pW = sWoT + px * 256 + pk * 64;

    // precomputed cp.async smem dst addresses (4 per chunk)
    unsigned dst0[4], dst1[4];
    #pragma unroll
    for (int it = 0; it < 4; it++) {
        int kA = it * 32 + k_me;
        dst0[it] = (unsigned)__cvta_generic_to_shared(sAct + (size_t)kA * 36 + q_me * 4);
        dst1[it] = (unsigned)__cvta_generic_to_shared(sAct + (size_t)(kA + 128) * 36 + q_me * 4);
    }

    for (int i = 0; i < TT; i++) {
        const float2* srcP = g_pair + (size_t)i * HB;

        // ---- hoisted skip-ring reads + next-step constants (same-thread data).
        const int pi_ = sPI[i];
        float sp = (pi_ < 0) ? 0.f : sHist[(pi_ & 15) * 256 + tid];
        const int ip  = i + 1;
        const int ipc = (ip < TT) ? ip : (TT - 1);
        const int gi_ = sGI[ipc];
        float sg = (gi_ < 0) ? 0.f : sHist[(gi_ & 15) * 256 + tid];
        const float m0v = sM0[ipc], m1v = sM1[ipc];

        unsigned tgt = 8u * (unsigned)i;
        unsigned v;

        // ---- wait for low-half producers, stage chunk0 ----
        do {
            asm volatile("ld.acquire.gpu.u32 %0, [%1];" : "=r"(v) : "l"(ctrL));
        } while ((int)(v - tgt) < 0);
        #pragma unroll
        for (int it = 0; it < 4; it++) {
            int k = it * 32 + k_me;
            CP_ASYNC16(dst0[it], (const void*)(srcP + (size_t)k * BB + b0 + q_me * 2));
        }
        CP_COMMIT();

        // ---- wait for high-half producers, stage chunk1 ----
        do {
            asm volatile("ld.acquire.gpu.u32 %0, [%1];" : "=r"(v) : "l"(ctrH));
        } while ((int)(v - tgt) < 0);
        #pragma unroll
        for (int it = 0; it < 4; it++) {
            int k = 128 + it * 32 + k_me;
            CP_ASYNC16(dst1[it], (const void*)(srcP + (size_t)k * BB + b0 + q_me * 2));
        }
        CP_COMMIT();

        CP_WAIT(1);                             // chunk0 landed
        __syncthreads();

        // ---- GEMM phase A: j = 0..15 (k = kq+8j < 128) ----
        ull acc[2][4][3];
        #pragma unroll
        for (int hh = 0; hh < 2; hh++)
            #pragma unroll
            for (int bb = 0; bb < 4; bb++)
                #pragma unroll
                for (int g = 0; g < 3; g++) acc[hh][bb][g] = 0ull;

        #pragma unroll
        for (int j = 0; j < 16; j++) {
            int k = kq + 8 * j;
            const float* a = ap0 + (size_t)k * 36;
            ulonglong2 aA = *(const ulonglong2*)a;
            ulonglong2 aB = *(const ulonglong2*)(a + 4);
            const float* w0 = wA + (size_t)k * 128;
            const float* w1 = wB + (size_t)k * 128;
            ulonglong2 w0A = *(const ulonglong2*)w0;
            ull        w0n = *(const ull*)(w0 + 4);
            ulonglong2 w1A = *(const ulonglong2*)w1;
            ull        w1n = *(const ull*)(w1 + 4);
            ull av[4] = {aA.x, aA.y, aB.x, aB.y};
            #pragma unroll
            for (int bb = 0; bb < 4; bb++) {
                FMA2(acc[0][bb][0], av[bb], w0A.x);
                FMA2(acc[0][bb][1], av[bb], w0A.y);
                FMA2(acc[0][bb][2], av[bb], w0n);
                FMA2(acc[1][bb][0], av[bb], w1A.x);
                FMA2(acc[1][bb][1], av[bb], w1A.y);
                FMA2(acc[1][bb][2], av[bb], w1n);
            }
        }

        CP_WAIT(0);                             // chunk1 landed (was in flight)
        __syncthreads();

        #pragma unroll
        for (int j = 16; j < 32; j++) {
            int k = kq + 8 * j;
            const float* a = ap0 + (size_t)k * 36;
            ulonglong2 aA = *(const ulonglong2*)a;
            ulonglong2 aB = *(const ulonglong2*)(a + 4);
            const float* w0 = wA + (size_t)k * 128;
            const float* w1 = wB + (size_t)k * 128;
            ulonglong2 w0A = *(const ulonglong2*)w0;
            ull        w0n = *(const ull*)(w0 + 4);
            ulonglong2 w1A = *(const ulonglong2*)w1;
            ull        w1n = *(const ull*)(w1 + 4);
            ull av[4] = {aA.x, aA.y, aB.x, aB.y};
            #pragma unroll
            for (int bb = 0; bb < 4; bb++) {
                FMA2(acc[0][bb][0], av[bb], w0A.x);
                FMA2(acc[0][bb][1], av[bb], w0A.y);
                FMA2(acc[0][bb][2], av[bb], w0n);
                FMA2(acc[1][bb][0], av[bb], w1A.x);
                FMA2(acc[1][bb][1], av[bb], w1A.y);
                FMA2(acc[1][bb][2], av[bb], w1n);
            }
        }

        // ---- 3-level halving butterfly across k slices (within warp) ----
        ull r1[2][2][3];
        #pragma unroll
        for (int hh = 0; hh < 2; hh++)
            #pragma unroll
            for (int bp = 0; bp < 2; bp++)
                #pragma unroll
                for (int g = 0; g < 3; g++) {
                    ull x = acc[hh][bp * 2][g], y = acc[hh][bp * 2 + 1][g];
                    ull give = kb0 ? x : y;
                    ull keep = kb0 ? y : x;
                    ull rec = __shfl_xor_sync(0xffffffffu, give, 4);
                    ADD2(r1[hh][bp][g], keep, rec);
                }
        ull r2[2][3];
        #pragma unroll
        for (int hh = 0; hh < 2; hh++)
            #pragma unroll
            for (int g = 0; g < 3; g++) {
                ull x = r1[hh][0][g], y = r1[hh][1][g];
                ull give = kb1 ? x : y;
                ull keep = kb1 ? y : x;
                ull rec = __shfl_xor_sync(0xffffffffu, give, 8);
                ADD2(r2[hh][g], keep, rec);
            }
        ull r3[3];
        #pragma unroll
        for (int g = 0; g < 3; g++) {
            ull x = r2[0][g], y = r2[1][g];
            ull give = kb2 ? x : y;
            ull keep = kb2 ? y : x;
            ull rec = __shfl_xor_sync(0xffffffffu, give, 16);
            ADD2(r3[g], keep, rec);
        }

        // ---- GRU epilogue: every thread owns exactly one cell ----
        {
            const float cbr = i ? crN : cr0;
            const float cbz = i ? czN : cz0;
            const float cbn = i ? cnN : cn0;
            float pre_r = lo32(r3[0]) + hi32(r3[0]) + cbr;
            float pre_z = lo32(r3[1]) + hi32(r3[1]) + cbz;
            float ghn   = lo32(r3[2]) + bhh_n;
            float rg = __fdividef(1.f, 1.f + __expf(-pre_r));
            float zg = __fdividef(1.f, 1.f + __expf(-pre_z));
            float pre_n = hi32(r3[2]) + cbn + rg * ghn;
            pre_n = fminf(fmaxf(pre_n, -15.f), 15.f);
            float e2 = __expf(2.f * pre_n);
            float ng = __fdividef(e2 - 1.f, e2 + 1.f);
            float h_new = (1.f - zg) * ng + zg * hid_own;

            // early-step overrides: table references the value appended THIS step
            if (pi_ == i) sp = h_new;           // only i==3
            if (gi_ == i) sg = h_new;           // only i==2
            float hbv  = h_prev + sp;                        // hb_i
            float hidn = m0v * h_new + m1v * sg;             // hidden_{i+1}

            g_pair[(size_t)ip * HB + off] = make_float2(hidn, hbv);  // one STG.64
            sHist[(i & 15) * 256 + tid] = h_new;             // off critical path
            hid_own = hidn;
            h_prev = h_new;
        }

        // ---- CTA-level release-arrive on this CTA's half-counter ----
        __syncthreads();
        if (tid == 0)
            asm volatile("red.release.gpu.global.add.u32 [%0], %1;"
                         :: "l"(myCtr), "r"(1u) : "memory");

        // ---- fused output projection (inside poll window, off critical path):
        //      sAct's hb lanes currently hold hb_{i-1} -> out[t = i-1]
        if (i) {
            float pacc = 0.f;
            #pragma unroll 8
            for (int j = 0; j < 64; j++)
                pacc += pA[j * 36] * pW[j];
            sRed[pb * 16 + px * 4 + pk] = pacc;
            __syncthreads();                    // also guards sAct vs next staging
            if (tid < 64) {
                float4 p4 = *(const float4*)&sRed[tid * 4];
                float o = p4.x + p4.y + p4.z + p4.w + sBo[tid & 3];
                int b = b0 + (tid >> 2);
                out[(size_t)b * TT * XX + (size_t)(i - 1) * XX + hgrp * 4 + (tid & 3)] = o;
            }
        }
    }
}

// ---------------- K_out: out[b][t][x] for remaining t (t = t0 + blockIdx.x) --------
#define SMEM_OUT ((16384 + 8192) * 4)
__global__ void __launch_bounds__(256)
k_out(float* __restrict__ out, const float* __restrict__ b_out, int t0)
{
    extern __shared__ float s[];
    float* sWo = s;              // [256h][64x]
    float* sA  = s + 16384;      // [64h][128b]
    const int t = t0 + blockIdx.x;
    const int tid = threadIdx.x;
    const int bgl = tid & 31, xg = tid >> 5;

    for (int idx = tid; idx < 16384; idx += 256) sWo[idx] = g_WoT[idx];
    float bo[8];
    #pragma unroll
    for (int xi = 0; xi < 8; xi++) bo[xi] = b_out[xg * 8 + xi];

    float acc[4][8];
    #pragma unroll
    for (int a = 0; a < 4; a++)
        #pragma unroll
        for (int cc = 0; cc < 8; cc++) acc[a][cc] = 0.f;

    const float2* src = g_pair + (size_t)(t + 1) * HB;   // hb_t = .y
    for (int c = 0; c < 4; c++) {
        __syncthreads();
        for (int idx = tid; idx < 4096; idx += 256) {
            float4 v = __ldcg((const float4*)(src + c * 8192 + idx * 2));
            sA[idx * 2]     = v.y;
            sA[idx * 2 + 1] = v.w;
        }
        __syncthreads();
        #pragma unroll 4
        for (int hh = 0; hh < 64; hh++) {
            float4 a4 = *(const float4*)&sA[hh * BB + bgl * 4];
            const float* wr = &sWo[(c * 64 + hh) * XX + xg * 8];
            float4 w0 = *(const float4*)wr;
            float4 w1 = *(const float4*)(wr + 4);
            float av[4] = {a4.x, a4.y, a4.z, a4.w};
            float wv[8] = {w0.x, w0.y, w0.z, w0.w, w1.x, w1.y, w1.z, w1.w};
            #pragma unroll
            for (int bi = 0; bi < 4; bi++)
                #pragma unroll
                for (int xi = 0; xi < 8; xi++)
                    acc[bi][xi] += av[bi] * wv[xi];
        }
    }
    #pragma unroll
    for (int bi = 0; bi < 4; bi++) {
        int b = bgl * 4 + bi;
        float* dst = out + (size_t)b * TT * XX + (size_t)t * XX + xg * 8;
        #pragma unroll
        for (int xi = 0; xi < 8; xi++) dst[xi] = acc[bi][xi] + bo[xi];
    }
}

// ---------------- host launch ----------------
extern "C" void kernel_launch(void* const* d_in, const int* in_sizes, int n_in,
                              void* d_out, int out_size)
{
    const float* h_enc = (const float*)d_in[1];
    const float* W_ih  = (const float*)d_in[2];
    const float* W_hh  = (const float*)d_in[3];
    const float* b_ih  = (const float*)d_in[4];
    const float* b_hh  = (const float*)d_in[5];
    const float* W_out = (const float*)d_in[6];
    const float* b_out = (const float*)d_in[7];
    const int*   mask0 = (const int*)d_in[8];
    const int*   mask1 = (const int*)d_in[9];
    const int*   skipp = (n_in > 10) ? (const int*)d_in[10] : nullptr;

    cudaFuncSetAttribute(k_main, cudaFuncAttributeMaxDynamicSharedMemorySize, SMEM_MAIN);
    cudaFuncSetAttribute(k_out,  cudaFuncAttributeMaxDynamicSharedMemorySize, SMEM_OUT);

    k_wc<<<G3 + 64, 256>>>(W_ih, W_out);
    k_init_tables<<<1, 256>>>(mask0, mask1, skipp, W_ih, b_ih, b_out);
    k_init_state<<<128, 256>>>(h_enc, mask0);
    k_main<<<128, 256, SMEM_MAIN>>>(W_hh, b_ih, b_hh, h_enc,
                                    (float*)d_out, b_out);
    k_out<<<1, 256, SMEM_OUT>>>((float*)d_out, b_out, TT - 1);   // only t = 511
}

// round 15
// speedup vs baseline: 1.0427x; 1.0427x over previous
#include <cuda_runtime.h>
#include <math.h>

#define BB   128            // batch
#define TT   512            // time steps
#define HH   256            // hidden
#define XX   64             // feature / output
#define G3   768            // 3*H
#define HB   (HH * BB)      // 32768 cells per map

// ---------------- device scratch (static: no runtime allocation) ----------------
__device__ float2 g_pair[(size_t)(TT + 1) * HB]; // slot i: {hidden_i, hb_{i-1}} [t][h][b]
__device__ float g_Wc [G3 * HH];                // W_ih @ W_out   [768][256]
__device__ float g_WoT[HH * XX];                // W_out transposed [h][x]
__device__ float g_bc [G3];                     // b_ih + W_ih @ b_out
__device__ float g_m0f[TT], g_m1f[TT];
__device__ int   g_gidx[TT], g_pidx[TT];        // -1 => zero placeholder
__device__ unsigned g_ctr[8 * 64];              // per-group split counters: [bg*64]=low, [bg*64+16]=high

typedef unsigned long long ull;

// ---------------- packed f32x2 ops (Blackwell) ----------------
#define FMA2(d, a, b) asm("fma.rn.f32x2 %0, %1, %2, %3;" \
                          : "=l"(d) : "l"(a), "l"(b), "l"(d))
#define ADD2(d, a, b) asm("add.rn.f32x2 %0, %1, %2;" \
                          : "=l"(d) : "l"(a), "l"(b))
#define DUP2(d, a) asm("mov.b64 %0, {%1, %1};" : "=l"(d) : "f"(a))
__device__ __forceinline__ float lo32(ull v) {
    return __uint_as_float((unsigned)(v & 0xffffffffull));
}
__device__ __forceinline__ float hi32(ull v) {
    return __uint_as_float((unsigned)(v >> 32));
}

#define CP_ASYNC16(smem_u32, gptr) \
    asm volatile("cp.async.cg.shared.global [%0], [%1], 16;" \
                 :: "r"(smem_u32), "l"(gptr) : "memory")
#define CP_COMMIT()   asm volatile("cp.async.commit_group;" ::: "memory")
#define CP_WAIT(n)    asm volatile("cp.async.wait_group %0;" :: "n"(n) : "memory")

// ---------------- K_wc: Wc = W_ih @ W_out  + W_out transpose ----------------
__global__ void k_wc(const float* __restrict__ W_ih, const float* __restrict__ W_out)
{
    int j = blockIdx.x;
    int k = threadIdx.x;
    if (j < G3) {
        float acc = 0.f;
        #pragma unroll
        for (int x = 0; x < XX; x++)
            acc += W_ih[j * XX + x] * W_out[x * HH + k];
        g_Wc[j * HH + k] = acc;
    } else {
        int idx = (j - G3) * 256 + k;
        int h = idx >> 6, x = idx & 63;
        g_WoT[h * XX + x] = W_out[x * HH + h];
    }
}

// ---------------- K_tab: tables + composed bias ----------------
__global__ void k_init_tables(const int* __restrict__ mask0, const int* __restrict__ mask1,
                              const int* skipp,
                              const float* __restrict__ W_ih, const float* __restrict__ b_ih,
                              const float* __restrict__ b_out)
{
    int tid = threadIdx.x;
    int skip = skipp ? skipp[0] : 4;
    for (int i = tid; i < TT; i += 256) {
        g_m0f[i] = (float)mask0[i];
        g_m1f[i] = (float)mask1[i];
        int pg = (i < skip) ? 2 * i : i - skip;
        g_gidx[i] = (pg < skip) ? -1 : (pg - skip);
        int pp = (i < skip) ? 2 * i + 1 : i - skip;
        g_pidx[i] = (pp < skip) ? -1 : (pp - skip);
    }
    for (int j = tid; j < G3; j += 256) {
        float acc = b_ih[j];
        for (int x = 0; x < XX; x++) acc += W_ih[j * XX + x] * b_out[x];
        g_bc[j] = acc;
    }
}

// ---------------- K_state: init pair slot 0 + counters ----------------
__global__ void k_init_state(const float* __restrict__ h_enc, const int* __restrict__ mask0)
{
    int idx = blockIdx.x * 256 + threadIdx.x;   // 0..32767
    int h = idx >> 7, b = idx & 127;
    float m0 = (float)mask0[0];
    g_pair[idx] = make_float2(m0 * h_enc[b * HH + h], 0.f); // {hidden_0, hb_{-1}=0}
    if (idx < 8 * 64) g_ctr[idx] = 0u;
}

// ---------------- K_main: persistent recurrence, register-blocked, cp.async staged --
// (R12 engine verbatim — best measured configuration)
#define SW_F    (256 * 128)
#define SACT_F  (256 * 36)
#define SHIST_F (16 * 256)
#define SMEM_MAIN ((SW_F + SACT_F + SHIST_F + 4 * TT) * 4)

__global__ void __launch_bounds__(256, 1)
k_main(const float* __restrict__ W_hh, const float* __restrict__ b_ih,
       const float* __restrict__ b_hh, const float* __restrict__ h_enc)
{
    extern __shared__ float sm[];
    float* sW    = sm;
    float* sAct  = sW + SW_F;
    float* sHist = sAct + SACT_F;
    float* sM0   = sHist + SHIST_F;
    float* sM1   = sM0 + TT;
    int*   sGI   = (int*)(sM1 + TT);
    int*   sPI   = sGI + TT;

    const int tid = threadIdx.x;
    const int bq  = tid & 3;
    const int kq  = (tid >> 2) & 7;
    const int hg  = tid >> 5;                   // warp id
    const int bg  = blockIdx.x >> 4;            // batch group
    const int hgrp= blockIdx.x & 15;
    const int b0  = bg * 16;
    const int h0  = hgrp * 16;
    const int kb0 = kq & 1, kb1 = (kq >> 1) & 1, kb2 = kq >> 2;

    // owned cell for epilogue
    const int h_m = h0 + hg * 2 + kb2;
    const int b_l = bq * 4 + (kq & 3);
    const int b_m = b0 + b_l;
    const int off = h_m * BB + b_m;             // [h][b] within a pair slot

    // ---- stage weight slice once ----
    for (int idx = tid; idx < 256 * 16; idx += 256) {
        int k = idx >> 4, hl = idx & 15;
        float* d = sW + (size_t)k * 128 + ((hl * 8) ^ ((k & 7) * 8));
        #pragma unroll
        for (int g = 0; g < 3; g++) {
            int row = g * HH + h0 + hl;
            d[2 * g]     = W_hh[row * HH + k];
            d[2 * g + 1] = g_Wc[row * HH + k];
        }
    }
    for (int idx = tid; idx < TT; idx += 256) {
        sM0[idx] = g_m0f[idx]; sM1[idx] = g_m1f[idx];
        sGI[idx] = g_gidx[idx]; sPI[idx] = g_pidx[idx];
    }

    // per-owned-cell bias constants
    const float bhh_n = b_hh[2 * HH + h_m];
    const float cr0 = b_hh[h_m]      + b_ih[h_m];
    const float cz0 = b_hh[HH + h_m] + b_ih[HH + h_m];
    const float cn0 = b_ih[2 * HH + h_m];
    const float crN = b_hh[h_m]      + g_bc[h_m];
    const float czN = b_hh[HH + h_m] + g_bc[HH + h_m];
    const float cnN = g_bc[2 * HH + h_m];

    float h_prev  = h_enc[b_m * HH + h_m];
    float hid_own = g_m0f[0] * h_prev;
    __syncthreads();

    unsigned* ctrL = &g_ctr[bg * 64];           // low-h producers (hgrp 0..7)
    unsigned* ctrH = &g_ctr[bg * 64 + 16];      // high-h producers (hgrp 8..15)
    unsigned* myCtr = (hgrp < 8) ? ctrL : ctrH;

    const float* ap0 = sAct + bq * 8;                    // + (kq+8j)*36 per j
    const float* wA  = sW + ((hg * 16) ^ (kq * 8));      // + (kq+8j)*128 per j
    const float* wB  = sW + (((hg * 16) ^ (kq * 8)) ^ 8);
    const int q_me   = tid & 7;                          // staging lane mapping
    const int k_me   = tid >> 3;                         // 0..31 within a 256-thread pass

    // precomputed cp.async smem dst addresses (4 per chunk)
    unsigned dst0[4], dst1[4];
    #pragma unroll
    for (int it = 0; it < 4; it++) {
        int kA = it * 32 + k_me;
        dst0[it] = (unsigned)__cvta_generic_to_shared(sAct + (size_t)kA * 36 + q_me * 4);
        dst1[it] = (unsigned)__cvta_generic_to_shared(sAct + (size_t)(kA + 128) * 36 + q_me * 4);
    }

    for (int i = 0; i < TT; i++) {
        const float2* srcP = g_pair + (size_t)i * HB;

        // ---- hoisted skip-ring reads + next-step constants (same-thread data).
        const int pi_ = sPI[i];
        float sp = (pi_ < 0) ? 0.f : sHist[(pi_ & 15) * 256 + tid];
        const int ip  = i + 1;
        const int ipc = (ip < TT) ? ip : (TT - 1);
        const int gi_ = sGI[ipc];
        float sg = (gi_ < 0) ? 0.f : sHist[(gi_ & 15) * 256 + tid];
        const float m0v = sM0[ipc], m1v = sM1[ipc];

        unsigned tgt = 8u * (unsigned)i;
        unsigned v;

        // ---- wait for low-half producers, stage chunk0 ----
        do {
            asm volatile("ld.acquire.gpu.u32 %0, [%1];" : "=r"(v) : "l"(ctrL));
        } while ((int)(v - tgt) < 0);
        #pragma unroll
        for (int it = 0; it < 4; it++) {
            int k = it * 32 + k_me;
            CP_ASYNC16(dst0[it], (const void*)(srcP + (size_t)k * BB + b0 + q_me * 2));
        }
        CP_COMMIT();

        // ---- wait for high-half producers, stage chunk1 ----
        do {
            asm volatile("ld.acquire.gpu.u32 %0, [%1];" : "=r"(v) : "l"(ctrH));
        } while ((int)(v - tgt) < 0);
        #pragma unroll
        for (int it = 0; it < 4; it++) {
            int k = 128 + it * 32 + k_me;
            CP_ASYNC16(dst1[it], (const void*)(srcP + (size_t)k * BB + b0 + q_me * 2));
        }
        CP_COMMIT();

        CP_WAIT(1);                             // chunk0 landed
        __syncthreads();

        // ---- GEMM phase A: j = 0..15 (k = kq+8j < 128) ----
        ull acc[2][4][3];
        #pragma unroll
        for (int hh = 0; hh < 2; hh++)
            #pragma unroll
            for (int bb = 0; bb < 4; bb++)
                #pragma unroll
                for (int g = 0; g < 3; g++) acc[hh][bb][g] = 0ull;

        #pragma unroll
        for (int j = 0; j < 16; j++) {
            int k = kq + 8 * j;
            const float* a = ap0 + (size_t)k * 36;
            ulonglong2 aA = *(const ulonglong2*)a;
            ulonglong2 aB = *(const ulonglong2*)(a + 4);
            const float* w0 = wA + (size_t)k * 128;
            const float* w1 = wB + (size_t)k * 128;
            ulonglong2 w0A = *(const ulonglong2*)w0;
            ull        w0n = *(const ull*)(w0 + 4);
            ulonglong2 w1A = *(const ulonglong2*)w1;
            ull        w1n = *(const ull*)(w1 + 4);
            ull av[4] = {aA.x, aA.y, aB.x, aB.y};
            #pragma unroll
            for (int bb = 0; bb < 4; bb++) {
                FMA2(acc[0][bb][0], av[bb], w0A.x);
                FMA2(acc[0][bb][1], av[bb], w0A.y);
                FMA2(acc[0][bb][2], av[bb], w0n);
                FMA2(acc[1][bb][0], av[bb], w1A.x);
                FMA2(acc[1][bb][1], av[bb], w1A.y);
                FMA2(acc[1][bb][2], av[bb], w1n);
            }
        }

        CP_WAIT(0);                             // chunk1 landed (was in flight)
        __syncthreads();

        #pragma unroll
        for (int j = 16; j < 32; j++) {
            int k = kq + 8 * j;
            const float* a = ap0 + (size_t)k * 36;
            ulonglong2 aA = *(const ulonglong2*)a;
            ulonglong2 aB = *(const ulonglong2*)(a + 4);
            const float* w0 = wA + (size_t)k * 128;
            const float* w1 = wB + (size_t)k * 128;
            ulonglong2 w0A = *(const ulonglong2*)w0;
            ull        w0n = *(const ull*)(w0 + 4);
            ulonglong2 w1A = *(const ulonglong2*)w1;
            ull        w1n = *(const ull*)(w1 + 4);
            ull av[4] = {aA.x, aA.y, aB.x, aB.y};
            #pragma unroll
            for (int bb = 0; bb < 4; bb++) {
                FMA2(acc[0][bb][0], av[bb], w0A.x);
                FMA2(acc[0][bb][1], av[bb], w0A.y);
                FMA2(acc[0][bb][2], av[bb], w0n);
                FMA2(acc[1][bb][0], av[bb], w1A.x);
                FMA2(acc[1][bb][1], av[bb], w1A.y);
                FMA2(acc[1][bb][2], av[bb], w1n);
            }
        }

        // ---- 3-level halving butterfly across k slices (within warp) ----
        ull r1[2][2][3];
        #pragma unroll
        for (int hh = 0; hh < 2; hh++)
            #pragma unroll
            for (int bp = 0; bp < 2; bp++)
                #pragma unroll
                for (int g = 0; g < 3; g++) {
                    ull x = acc[hh][bp * 2][g], y = acc[hh][bp * 2 + 1][g];
                    ull give = kb0 ? x : y;
                    ull keep = kb0 ? y : x;
                    ull rec = __shfl_xor_sync(0xffffffffu, give, 4);
                    ADD2(r1[hh][bp][g], keep, rec);
                }
        ull r2[2][3];
        #pragma unroll
        for (int hh = 0; hh < 2; hh++)
            #pragma unroll
            for (int g = 0; g < 3; g++) {
                ull x = r1[hh][0][g], y = r1[hh][1][g];
                ull give = kb1 ? x : y;
                ull keep = kb1 ? y : x;
                ull rec = __shfl_xor_sync(0xffffffffu, give, 8);
                ADD2(r2[hh][g], keep, rec);
            }
        ull r3[3];
        #pragma unroll
        for (int g = 0; g < 3; g++) {
            ull x = r2[0][g], y = r2[1][g];
            ull give = kb2 ? x : y;
            ull keep = kb2 ? y : x;
            ull rec = __shfl_xor_sync(0xffffffffu, give, 16);
            ADD2(r3[g], keep, rec);
        }

        // ---- GRU epilogue: every thread owns exactly one cell ----
        {
            const float cbr = i ? crN : cr0;
            const float cbz = i ? czN : cz0;
            const float cbn = i ? cnN : cn0;
            float pre_r = lo32(r3[0]) + hi32(r3[0]) + cbr;
            float pre_z = lo32(r3[1]) + hi32(r3[1]) + cbz;
            float ghn   = lo32(r3[2]) + bhh_n;
            float rg = __fdividef(1.f, 1.f + __expf(-pre_r));
            float zg = __fdividef(1.f, 1.f + __expf(-pre_z));
            float pre_n = hi32(r3[2]) + cbn + rg * ghn;
            pre_n = fminf(fmaxf(pre_n, -15.f), 15.f);
            float e2 = __expf(2.f * pre_n);
            float ng = __fdividef(e2 - 1.f, e2 + 1.f);
            float h_new = (1.f - zg) * ng + zg * hid_own;

            // early-step overrides: table references the value appended THIS step
            if (pi_ == i) sp = h_new;           // only i==3
            if (gi_ == i) sg = h_new;           // only i==2
            float hbv  = h_prev + sp;                        // hb_i
            float hidn = m0v * h_new + m1v * sg;             // hidden_{i+1}

            g_pair[(size_t)ip * HB + off] = make_float2(hidn, hbv);  // one STG.64
            sHist[(i & 15) * 256 + tid] = h_new;             // off critical path
            hid_own = hidn;
            h_prev = h_new;
        }

        // ---- CTA-level release-arrive on this CTA's half-counter ----
        __syncthreads();
        if (tid == 0)
            asm volatile("red.release.gpu.global.add.u32 [%0], %1;"
                         :: "l"(myCtr), "r"(1u) : "memory");
    }
}

// ---------------- K_out: out[b][t][x] = hb_t . W_out[x] + b_out  (f32x2 packed x) --
#define SMEM_OUT ((16384 + 8192) * 4)
__global__ void __launch_bounds__(256)
k_out(float* __restrict__ out, const float* __restrict__ b_out)
{
    extern __shared__ float s[];
    float* sWo = s;              // [256h][64x]
    float* sA  = s + 16384;      // [64h][128b]
    const int t = blockIdx.x;
    const int tid = threadIdx.x;
    const int bgl = tid & 31, xg = tid >> 5;

    for (int idx = tid; idx < 16384; idx += 256) sWo[idx] = g_WoT[idx];
    float bo[8];
    #pragma unroll
    for (int xi = 0; xi < 8; xi++) bo[xi] = b_out[xg * 8 + xi];

    // packed accumulators: acc2[bi][xp] holds x-pair (2*xp, 2*xp+1)
    ull acc2[4][4];
    #pragma unroll
    for (int bi = 0; bi < 4; bi++)
        #pragma unroll
        for (int xp = 0; xp < 4; xp++) acc2[bi][xp] = 0ull;

    const float2* src = g_pair + (size_t)(t + 1) * HB;   // hb_t = .y
    for (int c = 0; c < 4; c++) {
        __syncthreads();
        for (int idx = tid; idx < 4096; idx += 256) {
            float4 v = __ldcg((const float4*)(src + c * 8192 + idx * 2));
            sA[idx * 2]     = v.y;
            sA[idx * 2 + 1] = v.w;
        }
        __syncthreads();
        #pragma unroll 4
        for (int hh = 0; hh < 64; hh++) {
            float4 a4 = *(const float4*)&sA[hh * BB + bgl * 4];
            const float* wr = &sWo[(c * 64 + hh) * XX + xg * 8];
            ulonglong2 wP0 = *(const ulonglong2*)wr;        // x-pairs 0,1
            ulonglong2 wP1 = *(const ulonglong2*)(wr + 4);  // x-pairs 2,3
            ull ad[4];
            DUP2(ad[0], a4.x); DUP2(ad[1], a4.y);
            DUP2(ad[2], a4.z); DUP2(ad[3], a4.w);
            #pragma unroll
            for (int bi = 0; bi < 4; bi++) {
                FMA2(acc2[bi][0], ad[bi], wP0.x);
                FMA2(acc2[bi][1], ad[bi], wP0.y);
                FMA2(acc2[bi][2], ad[bi], wP1.x);
                FMA2(acc2[bi][3], ad[bi], wP1.y);
            }
        }
    }
    #pragma unroll
    for (int bi = 0; bi < 4; bi++) {
        int b = bgl * 4 + bi;
        float* dst = out + (size_t)b * TT * XX + (size_t)t * XX + xg * 8;
        #pragma unroll
        for (int xp = 0; xp < 4; xp++) {
            dst[2 * xp]     = lo32(acc2[bi][xp]) + bo[2 * xp];
            dst[2 * xp + 1] = hi32(acc2[bi][xp]) + bo[2 * xp + 1];
        }
    }
}

// ---------------- host launch ----------------
extern "C" void kernel_launch(void* const* d_in, const int* in_sizes, int n_in,
                              void* d_out, int out_size)
{
    const float* h_enc = (const float*)d_in[1];
    const float* W_ih  = (const float*)d_in[2];
    const float* W_hh  = (const float*)d_in[3];
    const float* b_ih  = (const float*)d_in[4];
    const float* b_hh  = (const float*)d_in[5];
    const float* W_out = (const float*)d_in[6];
    const float* b_out = (const float*)d_in[7];
    const int*   mask0 = (const int*)d_in[8];
    const int*   mask1 = (const int*)d_in[9];
    const int*   skipp = (n_in > 10) ? (const int*)d_in[10] : nullptr;

    cudaFuncSetAttribute(k_main, cudaFuncAttributeMaxDynamicSharedMemorySize, SMEM_MAIN);
    cudaFuncSetAttribute(k_out,  cudaFuncAttributeMaxDynamicSharedMemorySize, SMEM_OUT);

    k_wc<<<G3 + 64, 256>>>(W_ih, W_out);
    k_init_tables<<<1, 256>>>(mask0, mask1, skipp, W_ih, b_ih, b_out);
    k_init_state<<<128, 256>>>(h_enc, mask0);
    k_main<<<128, 256, SMEM_MAIN>>>(W_hh, b_ih, b_hh, h_enc);
    k_out<<<TT, 256, SMEM_OUT>>>((float*)d_out, b_out);
}

// round 16
// speedup vs baseline: 1.0881x; 1.0436x over previous
#include <cuda_runtime.h>
#include <math.h>

#define BB   128            // batch
#define TT   512            // time steps
#define HH   256            // hidden
#define XX   64             // feature / output
#define G3   768            // 3*H
#define HB   (HH * BB)      // 32768 cells per map

// ---------------- device scratch (static: no runtime allocation) ----------------
__device__ float2 g_pair[(size_t)(TT + 1) * HB]; // slot i: {hidden_i, hb_{i-1}} [t][h][b]
__device__ float g_Wc [G3 * HH];                // W_ih @ W_out   [768][256]
__device__ float g_WoT[HH * XX];                // W_out transposed [h][x]
__device__ float g_bc [G3];                     // b_ih + W_ih @ b_out
__device__ float g_m0f[TT], g_m1f[TT];
__device__ int   g_gidx[TT], g_pidx[TT];        // -1 => zero placeholder
__device__ unsigned g_ctr[8 * 64];              // per-group split counters: [bg*64]=low, [bg*64+16]=high

typedef unsigned long long ull;

// ---------------- packed f32x2 ops (Blackwell) ----------------
#define FMA2(d, a, b) asm("fma.rn.f32x2 %0, %1, %2, %3;" \
                          : "=l"(d) : "l"(a), "l"(b), "l"(d))
#define ADD2(d, a, b) asm("add.rn.f32x2 %0, %1, %2;" \
                          : "=l"(d) : "l"(a), "l"(b))
#define DUP2(d, a) asm("mov.b64 %0, {%1, %1};" : "=l"(d) : "f"(a))
__device__ __forceinline__ float lo32(ull v) {
    return __uint_as_float((unsigned)(v & 0xffffffffull));
}
__device__ __forceinline__ float hi32(ull v) {
    return __uint_as_float((unsigned)(v >> 32));
}

#define CP_ASYNC16(smem_u32, gptr) \
    asm volatile("cp.async.cg.shared.global [%0], [%1], 16;" \
                 :: "r"(smem_u32), "l"(gptr) : "memory")
#define CP_COMMIT()   asm volatile("cp.async.commit_group;" ::: "memory")
#define CP_WAIT(n)    asm volatile("cp.async.wait_group %0;" :: "n"(n) : "memory")

// ---------------- K_wc: Wc = W_ih @ W_out  + W_out transpose ----------------
__global__ void k_wc(const float* __restrict__ W_ih, const float* __restrict__ W_out)
{
    int j = blockIdx.x;
    int k = threadIdx.x;
    if (j < G3) {
        float acc = 0.f;
        #pragma unroll
        for (int x = 0; x < XX; x++)
            acc += W_ih[j * XX + x] * W_out[x * HH + k];
        g_Wc[j * HH + k] = acc;
    } else {
        int idx = (j - G3) * 256 + k;
        int h = idx >> 6, x = idx & 63;
        g_WoT[h * XX + x] = W_out[x * HH + h];
    }
}

// ---------------- K_tab: tables + composed bias ----------------
__global__ void k_init_tables(const int* __restrict__ mask0, const int* __restrict__ mask1,
                              const int* skipp,
                              const float* __restrict__ W_ih, const float* __restrict__ b_ih,
                              const float* __restrict__ b_out)
{
    int tid = threadIdx.x;
    int skip = skipp ? skipp[0] : 4;
    for (int i = tid; i < TT; i += 256) {
        g_m0f[i] = (float)mask0[i];
        g_m1f[i] = (float)mask1[i];
        int pg = (i < skip) ? 2 * i : i - skip;
        g_gidx[i] = (pg < skip) ? -1 : (pg - skip);
        int pp = (i < skip) ? 2 * i + 1 : i - skip;
        g_pidx[i] = (pp < skip) ? -1 : (pp - skip);
    }
    for (int j = tid; j < G3; j += 256) {
        float acc = b_ih[j];
        for (int x = 0; x < XX; x++) acc += W_ih[j * XX + x] * b_out[x];
        g_bc[j] = acc;
    }
}

// ---------------- K_state: init pair slot 0 + counters ----------------
__global__ void k_init_state(const float* __restrict__ h_enc, const int* __restrict__ mask0)
{
    int idx = blockIdx.x * 256 + threadIdx.x;   // 0..32767
    int h = idx >> 7, b = idx & 127;
    float m0 = (float)mask0[0];
    g_pair[idx] = make_float2(m0 * h_enc[b * HH + h], 0.f); // {hidden_0, hb_{-1}=0}
    if (idx < 8 * 64) g_ctr[idx] = 0u;
}

// ---------------- K_main: recurrence CTAs (0..127) + projector CTAs (128..147) ----
// Recurrence engine = R12/R14 verbatim (best measured).
// Projectors: poll counters read-only, compute out[t] tiles as slots land.
#define SW_F    (256 * 128)
#define SACT_F  (256 * 36)
#define SHIST_F (16 * 256)
#define SMEM_MAIN ((SW_F + SACT_F + SHIST_F + 4 * TT) * 4)
#define NPROJ 20

__global__ void __launch_bounds__(256, 1)
k_main(const float* __restrict__ W_hh, const float* __restrict__ b_ih,
       const float* __restrict__ b_hh, const float* __restrict__ h_enc,
       float* __restrict__ out, const float* __restrict__ b_out)
{
    extern __shared__ float sm[];
    const int tid = threadIdx.x;

    if (blockIdx.x >= 128) {
        // ================= projector CTA =================
        float* sWo = sm;                   // [256h][64x] = 16384 floats
        float* sA  = sm + 16384;           // [256h][16b] = 4096 floats
        const int pcta = blockIdx.x - 128;
        const int b_l = tid & 15, xg = tid >> 4;   // thread: 1 b x 4 x

        for (int idx = tid; idx < 16384; idx += 256) sWo[idx] = g_WoT[idx];
        float bo0 = b_out[xg * 4 + 0], bo1 = b_out[xg * 4 + 1];
        float bo2 = b_out[xg * 4 + 2], bo3 = b_out[xg * 4 + 3];
        __syncthreads();

        for (int n = pcta; n < 8 * TT; n += NPROJ) {
            const int bgp = n & 7, t = n >> 3;
            if (tid == 0) {
                unsigned tgt = 8u * (unsigned)(t + 1);
                unsigned v;
                do {
                    asm volatile("ld.acquire.gpu.u32 %0, [%1];"
                                 : "=r"(v) : "l"(&g_ctr[bgp * 64]));
                } while ((int)(v - tgt) < 0);
                do {
                    asm volatile("ld.acquire.gpu.u32 %0, [%1];"
                                 : "=r"(v) : "l"(&g_ctr[bgp * 64 + 16]));
                } while ((int)(v - tgt) < 0);
            }
            __syncthreads();

            // stage hb tile: slot t+1, b in [bgp*16, +16), all 256 h
            const float2* src = g_pair + (size_t)(t + 1) * HB + bgp * 16;
            #pragma unroll
            for (int it = 0; it < 8; it++) {
                int idx = it * 256 + tid;          // 0..2047
                int h = idx >> 3, b2 = idx & 7;
                float4 v = __ldcg((const float4*)(src + (size_t)h * BB + b2 * 2));
                sA[h * 16 + b2 * 2]     = v.y;
                sA[h * 16 + b2 * 2 + 1] = v.w;
            }
            __syncthreads();

            // GEMM: out[b][4x] = sum_h sA[h][b] * sWo[h][4x]
            ull a0 = 0ull, a1 = 0ull;
            #pragma unroll 4
            for (int h = 0; h < HH; h++) {
                float av = sA[h * 16 + b_l];
                ull ad; DUP2(ad, av);
                ulonglong2 w = *(const ulonglong2*)&sWo[h * XX + xg * 4];
                FMA2(a0, ad, w.x);
                FMA2(a1, ad, w.y);
            }
            float* dst = out + (size_t)(bgp * 16 + b_l) * TT * XX
                             + (size_t)t * XX + xg * 4;
            dst[0] = lo32(a0) + bo0;
            dst[1] = hi32(a0) + bo1;
            dst[2] = lo32(a1) + bo2;
            dst[3] = hi32(a1) + bo3;
        }
        return;
    }

    // ================= recurrence CTA (R12/R14 engine, verbatim) =================
    float* sW    = sm;
    float* sAct  = sW + SW_F;
    float* sHist = sAct + SACT_F;
    float* sM0   = sHist + SHIST_F;
    float* sM1   = sM0 + TT;
    int*   sGI   = (int*)(sM1 + TT);
    int*   sPI   = sGI + TT;

    const int bq  = tid & 3;
    const int kq  = (tid >> 2) & 7;
    const int hg  = tid >> 5;                   // warp id
    const int bg  = blockIdx.x >> 4;            // batch group
    const int hgrp= blockIdx.x & 15;
    const int b0  = bg * 16;
    const int h0  = hgrp * 16;
    const int kb0 = kq & 1, kb1 = (kq >> 1) & 1, kb2 = kq >> 2;

    // owned cell for epilogue
    const int h_m = h0 + hg * 2 + kb2;
    const int b_l = bq * 4 + (kq & 3);
    const int b_m = b0 + b_l;
    const int off = h_m * BB + b_m;             // [h][b] within a pair slot

    // ---- stage weight slice once ----
    for (int idx = tid; idx < 256 * 16; idx += 256) {
        int k = idx >> 4, hl = idx & 15;
        float* d = sW + (size_t)k * 128 + ((hl * 8) ^ ((k & 7) * 8));
        #pragma unroll
        for (int g = 0; g < 3; g++) {
            int row = g * HH + h0 + hl;
            d[2 * g]     = W_hh[row * HH + k];
            d[2 * g + 1] = g_Wc[row * HH + k];
        }
    }
    for (int idx = tid; idx < TT; idx += 256) {
        sM0[idx] = g_m0f[idx]; sM1[idx] = g_m1f[idx];
        sGI[idx] = g_gidx[idx]; sPI[idx] = g_pidx[idx];
    }

    // per-owned-cell bias constants
    const float bhh_n = b_hh[2 * HH + h_m];
    const float cr0 = b_hh[h_m]      + b_ih[h_m];
    const float cz0 = b_hh[HH + h_m] + b_ih[HH + h_m];
    const float cn0 = b_ih[2 * HH + h_m];
    const float crN = b_hh[h_m]      + g_bc[h_m];
    const float czN = b_hh[HH + h_m] + g_bc[HH + h_m];
    const float cnN = g_bc[2 * HH + h_m];

    float h_prev  = h_enc[b_m * HH + h_m];
    float hid_own = g_m0f[0] * h_prev;
    __syncthreads();

    unsigned* ctrL = &g_ctr[bg * 64];           // low-h producers (hgrp 0..7)
    unsigned* ctrH = &g_ctr[bg * 64 + 16];      // high-h producers (hgrp 8..15)
    unsigned* myCtr = (hgrp < 8) ? ctrL : ctrH;

    const float* ap0 = sAct + bq * 8;                    // + (kq+8j)*36 per j
    const float* wA  = sW + ((hg * 16) ^ (kq * 8));      // + (kq+8j)*128 per j
    const float* wB  = sW + (((hg * 16) ^ (kq * 8)) ^ 8);
    const int q_me   = tid & 7;                          // staging lane mapping
    const int k_me   = tid >> 3;                         // 0..31 within a 256-thread pass

    // precomputed cp.async smem dst addresses (4 per chunk)
    unsigned dst0[4], dst1[4];
    #pragma unroll
    for (int it = 0; it < 4; it++) {
        int kA = it * 32 + k_me;
        dst0[it] = (unsigned)__cvta_generic_to_shared(sAct + (size_t)kA * 36 + q_me * 4);
        dst1[it] = (unsigned)__cvta_generic_to_shared(sAct + (size_t)(kA + 128) * 36 + q_me * 4);
    }

    for (int i = 0; i < TT; i++) {
        const float2* srcP = g_pair + (size_t)i * HB;

        // ---- hoisted skip-ring reads + next-step constants (same-thread data).
        const int pi_ = sPI[i];
        float sp = (pi_ < 0) ? 0.f : sHist[(pi_ & 15) * 256 + tid];
        const int ip  = i + 1;
        const int ipc = (ip < TT) ? ip : (TT - 1);
        const int gi_ = sGI[ipc];
        float sg = (gi_ < 0) ? 0.f : sHist[(gi_ & 15) * 256 + tid];
        const float m0v = sM0[ipc], m1v = sM1[ipc];

        unsigned tgt = 8u * (unsigned)i;
        unsigned v;

        // ---- wait for low-half producers, stage chunk0 ----
        do {
            asm volatile("ld.acquire.gpu.u32 %0, [%1];" : "=r"(v) : "l"(ctrL));
        } while ((int)(v - tgt) < 0);
        #pragma unroll
        for (int it = 0; it < 4; it++) {
            int k = it * 32 + k_me;
            CP_ASYNC16(dst0[it], (const void*)(srcP + (size_t)k * BB + b0 + q_me * 2));
        }
        CP_COMMIT();

        // ---- wait for high-half producers, stage chunk1 ----
        do {
            asm volatile("ld.acquire.gpu.u32 %0, [%1];" : "=r"(v) : "l"(ctrH));
        } while ((int)(v - tgt) < 0);
        #pragma unroll
        for (int it = 0; it < 4; it++) {
            int k = 128 + it * 32 + k_me;
            CP_ASYNC16(dst1[it], (const void*)(srcP + (size_t)k * BB + b0 + q_me * 2));
        }
        CP_COMMIT();

        CP_WAIT(1);                             // chunk0 landed
        __syncthreads();

        // ---- GEMM phase A: j = 0..15 (k = kq+8j < 128) ----
        ull acc[2][4][3];
        #pragma unroll
        for (int hh = 0; hh < 2; hh++)
            #pragma unroll
            for (int bb = 0; bb < 4; bb++)
                #pragma unroll
                for (int g = 0; g < 3; g++) acc[hh][bb][g] = 0ull;

        #pragma unroll
        for (int j = 0; j < 16; j++) {
            int k = kq + 8 * j;
            const float* a = ap0 + (size_t)k * 36;
            ulonglong2 aA = *(const ulonglong2*)a;
            ulonglong2 aB = *(const ulonglong2*)(a + 4);
            const float* w0 = wA + (size_t)k * 128;
            const float* w1 = wB + (size_t)k * 128;
            ulonglong2 w0A = *(const ulonglong2*)w0;
            ull        w0n = *(const ull*)(w0 + 4);
            ulonglong2 w1A = *(const ulonglong2*)w1;
            ull        w1n = *(const ull*)(w1 + 4);
            ull av[4] = {aA.x, aA.y, aB.x, aB.y};
            #pragma unroll
            for (int bb = 0; bb < 4; bb++) {
                FMA2(acc[0][bb][0], av[bb], w0A.x);
                FMA2(acc[0][bb][1], av[bb], w0A.y);
                FMA2(acc[0][bb][2], av[bb], w0n);
                FMA2(acc[1][bb][0], av[bb], w1A.x);
                FMA2(acc[1][bb][1], av[bb], w1A.y);
                FMA2(acc[1][bb][2], av[bb], w1n);
            }
        }

        CP_WAIT(0);                             // chunk1 landed (was in flight)
        __syncthreads();

        #pragma unroll
        for (int j = 16; j < 32; j++) {
            int k = kq + 8 * j;
            const float* a = ap0 + (size_t)k * 36;
            ulonglong2 aA = *(const ulonglong2*)a;
            ulonglong2 aB = *(const ulonglong2*)(a + 4);
            const float* w0 = wA + (size_t)k * 128;
            const float* w1 = wB + (size_t)k * 128;
            ulonglong2 w0A = *(const ulonglong2*)w0;
            ull        w0n = *(const ull*)(w0 + 4);
            ulonglong2 w1A = *(const ulonglong2*)w1;
            ull        w1n = *(const ull*)(w1 + 4);
            ull av[4] = {aA.x, aA.y, aB.x, aB.y};
            #pragma unroll
            for (int bb = 0; bb < 4; bb++) {
                FMA2(acc[0][bb][0], av[bb], w0A.x);
                FMA2(acc[0][bb][1], av[bb], w0A.y);
                FMA2(acc[0][bb][2], av[bb], w0n);
                FMA2(acc[1][bb][0], av[bb], w1A.x);
                FMA2(acc[1][bb][1], av[bb], w1A.y);
                FMA2(acc[1][bb][2], av[bb], w1n);
            }
        }

        // ---- 3-level halving butterfly across k slices (within warp) ----
        ull r1[2][2][3];
        #pragma unroll
        for (int hh = 0; hh < 2; hh++)
            #pragma unroll
            for (int bp = 0; bp < 2; bp++)
                #pragma unroll
                for (int g = 0; g < 3; g++) {
                    ull x = acc[hh][bp * 2][g], y = acc[hh][bp * 2 + 1][g];
                    ull give = kb0 ? x : y;
                    ull keep = kb0 ? y : x;
                    ull rec = __shfl_xor_sync(0xffffffffu, give, 4);
                    ADD2(r1[hh][bp][g], keep, rec);
                }
        ull r2[2][3];
        #pragma unroll
        for (int hh = 0; hh < 2; hh++)
            #pragma unroll
            for (int g = 0; g < 3; g++) {
                ull x = r1[hh][0][g], y = r1[hh][1][g];
                ull give = kb1 ? x : y;
                ull keep = kb1 ? y : x;
                ull rec = __shfl_xor_sync(0xffffffffu, give, 8);
                ADD2(r2[hh][g], keep, rec);
            }
        ull r3[3];
        #pragma unroll
        for (int g = 0; g < 3; g++) {
            ull x = r2[0][g], y = r2[1][g];
            ull give = kb2 ? x : y;
            ull keep = kb2 ? y : x;
            ull rec = __shfl_xor_sync(0xffffffffu, give, 16);
            ADD2(r3[g], keep, rec);
        }

        // ---- GRU epilogue: every thread owns exactly one cell ----
        {
            const float cbr = i ? crN : cr0;
            const float cbz = i ? czN : cz0;
            const float cbn = i ? cnN : cn0;
            float pre_r = lo32(r3[0]) + hi32(r3[0]) + cbr;
            float pre_z = lo32(r3[1]) + hi32(r3[1]) + cbz;
            float ghn   = lo32(r3[2]) + bhh_n;
            float rg = __fdividef(1.f, 1.f + __expf(-pre_r));
            float zg = __fdividef(1.f, 1.f + __expf(-pre_z));
            float pre_n = hi32(r3[2]) + cbn + rg * ghn;
            pre_n = fminf(fmaxf(pre_n, -15.f), 15.f);
            float e2 = __expf(2.f * pre_n);
            float ng = __fdividef(e2 - 1.f, e2 + 1.f);
            float h_new = (1.f - zg) * ng + zg * hid_own;

            // early-step overrides: table references the value appended THIS step
            if (pi_ == i) sp = h_new;           // only i==3
            if (gi_ == i) sg = h_new;           // only i==2
            float hbv  = h_prev + sp;                        // hb_i
            float hidn = m0v * h_new + m1v * sg;             // hidden_{i+1}

            g_pair[(size_t)ip * HB + off] = make_float2(hidn, hbv);  // one STG.64
            sHist[(i & 15) * 256 + tid] = h_new;             // off critical path
            hid_own = hidn;
            h_prev = h_new;
        }

        // ---- CTA-level release-arrive on this CTA's half-counter ----
        __syncthreads();
        if (tid == 0)
            asm volatile("red.release.gpu.global.add.u32 [%0], %1;"
                         :: "l"(myCtr), "r"(1u) : "memory");
    }
}

// ---------------- host launch ----------------
extern "C" void kernel_launch(void* const* d_in, const int* in_sizes, int n_in,
                              void* d_out, int out_size)
{
    const float* h_enc = (const float*)d_in[1];
    const float* W_ih  = (const float*)d_in[2];
    const float* W_hh  = (const float*)d_in[3];
    const float* b_ih  = (const float*)d_in[4];
    const float* b_hh  = (const float*)d_in[5];
    const float* W_out = (const float*)d_in[6];
    const float* b_out = (const float*)d_in[7];
    const int*   mask0 = (const int*)d_in[8];
    const int*   mask1 = (const int*)d_in[9];
    const int*   skipp = (n_in > 10) ? (const int*)d_in[10] : nullptr;

    cudaFuncSetAttribute(k_main, cudaFuncAttributeMaxDynamicSharedMemorySize, SMEM_MAIN);

    k_wc<<<G3 + 64, 256>>>(W_ih, W_out);
    k_init_tables<<<1, 256>>>(mask0, mask1, skipp, W_ih, b_ih, b_out);
    k_init_state<<<128, 256>>>(h_enc, mask0);
    k_main<<<128 + NPROJ, 256, SMEM_MAIN>>>(W_hh, b_ih, b_hh, h_enc,
                                            (float*)d_out, b_out);
}